// round 10
// baseline (speedup 1.0000x reference)
#include <cuda_runtime.h>
#include <math.h>

// EpochedFutureFill: B=256, T=32768, L=32768 -> n_fft = 65536 = 256*256.
// Four-step FFT convolution, register-resident 256-pt warp FFTs.
// R9: global twiddle tables (no per-block sincospif), float4 transposes,
//     __launch_bounds__(256,3) for occupancy.
#define T_LEN   32768
#define N_FFT   65536
#define NSIG    128
#define SCALE_INV (1.0f / 65536.0f)

__device__ float4 d_scr4[NSIG * N_FFT / 2];  // 64 MB workspace (16B aligned)
__device__ float2 d_Htmp[N_FFT];             // filter intermediate
__device__ float2 d_Hs[N_FFT];               // filter spectrum [p][q]
__device__ float2 d_t256g[256];              // W_256^j
__device__ float2 d_tlog[256];               // W_N^j

__device__ __forceinline__ float2 cmul(float2 a, float2 b) {
    return make_float2(a.x * b.x - a.y * b.y, a.x * b.y + a.y * b.x);
}
__device__ __forceinline__ float2 cmulc(float2 a, float2 b) {  // a * conj(b)
    return make_float2(a.x * b.x + a.y * b.y, a.y * b.x - a.x * b.y);
}
__device__ __forceinline__ void bfly_f(float2& lo, float2& hi, float2 w) {
    float2 a = lo, b = hi;
    lo = make_float2(a.x + b.x, a.y + b.y);
    hi = cmul(make_float2(a.x - b.x, a.y - b.y), w);
}
__device__ __forceinline__ void bfly_i(float2& lo, float2& hi, float2 w) {
    float2 t = cmulc(hi, w);
    float2 a = lo;
    lo = make_float2(a.x + t.x, a.y + t.y);
    hi = make_float2(a.x - t.x, a.y - t.y);
}

// One-time twiddle build (1 block, 256 threads).
__global__ void k_init() {
    int t = threadIdx.x;
    float sn, cs;
    sincospif(-(float)t / 128.0f, &sn, &cs);
    d_t256g[t] = make_float2(cs, sn);
    sincospif(-(float)t / 32768.0f, &sn, &cs);
    d_tlog[t] = make_float2(cs, sn);
}

// 256-pt forward DIF FFT, warp-register-resident. v[k] = point 32k+lane.
__device__ __forceinline__ void fft256_reg(float2 v[8],
                                           const float2* __restrict__ t256,
                                           int lane) {
#pragma unroll
    for (int k = 0; k < 4; ++k) bfly_f(v[k], v[k + 4], t256[32 * k + lane]);
    {
        float2 w0 = t256[2 * lane], w1 = t256[64 + 2 * lane];
        bfly_f(v[0], v[2], w0); bfly_f(v[1], v[3], w1);
        bfly_f(v[4], v[6], w0); bfly_f(v[5], v[7], w1);
    }
    {
        float2 w = t256[4 * lane];
        bfly_f(v[0], v[1], w); bfly_f(v[2], v[3], w);
        bfly_f(v[4], v[5], w); bfly_f(v[6], v[7], w);
    }
#pragma unroll
    for (int s = 0; s < 5; ++s) {
        const int d = 16 >> s;
        float2 w = t256[(lane & (d - 1)) * (128 / d)];
        const bool up = (lane & d) != 0;
#pragma unroll
        for (int k = 0; k < 8; ++k) {
            float tr = __shfl_xor_sync(0xffffffffu, v[k].x, d);
            float ti = __shfl_xor_sync(0xffffffffu, v[k].y, d);
            if (up) v[k] = cmul(make_float2(tr - v[k].x, ti - v[k].y), w);
            else    { v[k].x += tr; v[k].y += ti; }
        }
    }
}

// 256-pt inverse (unnormalized, x256), exact reverse graph.
__device__ __forceinline__ void ifft256_reg(float2 v[8],
                                            const float2* __restrict__ t256,
                                            int lane) {
#pragma unroll
    for (int s = 0; s < 5; ++s) {
        const int d = 1 << s;
        float2 w = t256[(lane & (d - 1)) * (128 / d)];
        const bool up = (lane & d) != 0;
#pragma unroll
        for (int k = 0; k < 8; ++k) {
            float2 x = v[k];
            if (up) x = cmulc(x, w);
            float tr = __shfl_xor_sync(0xffffffffu, x.x, d);
            float ti = __shfl_xor_sync(0xffffffffu, x.y, d);
            v[k] = up ? make_float2(tr - x.x, ti - x.y)
                      : make_float2(x.x + tr, x.y + ti);
        }
    }
    {
        float2 w = t256[4 * lane];
        bfly_i(v[0], v[1], w); bfly_i(v[2], v[3], w);
        bfly_i(v[4], v[5], w); bfly_i(v[6], v[7], w);
    }
    {
        float2 w0 = t256[2 * lane], w1 = t256[64 + 2 * lane];
        bfly_i(v[0], v[2], w0); bfly_i(v[1], v[3], w1);
        bfly_i(v[4], v[6], w0); bfly_i(v[5], v[7], w1);
    }
#pragma unroll
    for (int k = 0; k < 4; ++k) bfly_i(v[k], v[k + 4], t256[32 * k + lane]);
}

// ---------------------------------------------------------------------------
// Pass 1: FFT over n2, long twiddle, store d_scr[s][n1][p]. float4 loads.
// ---------------------------------------------------------------------------
__global__ void __launch_bounds__(256, 3) k_pass1(const float* __restrict__ x) {
    __shared__ float  sre[8][132], sim[8][132];
    __shared__ float2 t256[256], tlo[256];
    const int tid = threadIdx.x, sgn = blockIdx.y, n1b = blockIdx.x * 8;
    t256[tid] = d_t256g[tid];
    tlo[tid]  = d_tlog[tid];

    // 8 rows (n1) x 128 cols (n2) per plane = 1024 floats = 256 float4.
    // idx -> n1q = idx&1 (group of 4 n1), n2 = idx>>1.
    const float4* __restrict__ xr4 =
        (const float4*)(x + (size_t)(2 * sgn)     * T_LEN);
    const float4* __restrict__ xi4 =
        (const float4*)(x + (size_t)(2 * sgn + 1) * T_LEN);
    {
        int n1q = tid & 1, n2 = tid >> 1;
        int g4 = (n1b >> 2) + n1q + 64 * n2;   // float4 index
        float4 a = xr4[g4];
        sre[4*n1q+0][n2] = a.x; sre[4*n1q+1][n2] = a.y;
        sre[4*n1q+2][n2] = a.z; sre[4*n1q+3][n2] = a.w;
        float4 b = xi4[g4];
        sim[4*n1q+0][n2] = b.x; sim[4*n1q+1][n2] = b.y;
        sim[4*n1q+2][n2] = b.z; sim[4*n1q+3][n2] = b.w;
    }
    __syncthreads();

    const int w = tid >> 5, lane = tid & 31;
    float2 v[8];
#pragma unroll
    for (int k = 0; k < 4; ++k) {
        v[k]     = make_float2(sre[w][32 * k + lane], sim[w][32 * k + lane]);
        v[k + 4] = make_float2(0.f, 0.f);      // zero pad [T, N)
    }
    fft256_reg(v, t256, lane);

    const int n1 = n1b + w;
    float2* __restrict__ out =
        (float2*)d_scr4 + (size_t)sgn * N_FFT + (size_t)n1 * 256;
#pragma unroll
    for (int k = 0; k < 8; ++k) {
        int p  = 32 * k + lane;
        int k2 = __brev(p) >> 24;
        int e  = n1 * k2;                      // < 65536
        float2 wt = cmul(t256[e >> 8], tlo[e & 255]);   // W_N^{n1*k2}
        out[p] = cmul(v[k], wt);
    }
}

// ---------------------------------------------------------------------------
// Pass 2 (fused): fwd FFT over n1, multiply Hs, inverse FFT, un-twiddle.
// float4 global transposes (2 p per thread per op).
// ---------------------------------------------------------------------------
__global__ void __launch_bounds__(256, 3) k_pass2() {
    __shared__ float  sre[8][260], sim[8][260];   // 260 % 32 == 4
    __shared__ float2 t256[256], tlo[256];
    const int tid = threadIdx.x, sgn = blockIdx.y, pb = blockIdx.x * 8;
    t256[tid] = d_t256g[tid];
    tlo[tid]  = d_tlog[tid];

    float2* __restrict__ base = (float2*)d_scr4 + (size_t)sgn * N_FFT;
    // 8 p x 256 n1 = 2048 float2 = 1024 float4; jj = pair of p.
#pragma unroll
    for (int it = 0; it < 4; ++it) {
        int idx = tid + it * 256;
        int jj = idx & 3, n1 = idx >> 2;
        float4 t = *(const float4*)&base[(size_t)n1 * 256 + pb + 2 * jj];
        sre[2*jj  ][n1] = t.x;  sim[2*jj  ][n1] = t.y;
        sre[2*jj+1][n1] = t.z;  sim[2*jj+1][n1] = t.w;
    }
    __syncthreads();

    const int w = tid >> 5, lane = tid & 31;
    float2 v[8];
#pragma unroll
    for (int k = 0; k < 8; ++k)
        v[k] = make_float2(sre[w][32 * k + lane], sim[w][32 * k + lane]);
    __syncthreads();                           // reads done before overwrite

    fft256_reg(v, t256, lane);                 // over n1 -> positions q

    const int p = pb + w;
    const float2* __restrict__ H = d_Hs + (size_t)p * 256;
#pragma unroll
    for (int k = 0; k < 8; ++k) v[k] = cmul(v[k], H[32 * k + lane]);

    ifft256_reg(v, t256, lane);                // -> natural n1

    const int k2 = __brev(p) >> 24;
#pragma unroll
    for (int k = 0; k < 8; ++k) {
        int n1 = 32 * k + lane;
        int e  = n1 * k2;                      // < 65536
        float2 wt = cmul(t256[e >> 8], tlo[e & 255]);
        v[k] = cmulc(v[k], wt);                // * W_N^{-n1*k2}
    }

#pragma unroll
    for (int k = 0; k < 8; ++k) {
        sre[w][32 * k + lane] = v[k].x;
        sim[w][32 * k + lane] = v[k].y;
    }
    __syncthreads();
#pragma unroll
    for (int it = 0; it < 4; ++it) {
        int idx = tid + it * 256;
        int jj = idx & 3, n1 = idx >> 2;
        float4 t;
        t.x = sre[2*jj  ][n1];  t.y = sim[2*jj  ][n1];
        t.z = sre[2*jj+1][n1];  t.w = sim[2*jj+1][n1];
        *(float4*)&base[(size_t)n1 * 256 + pb + 2 * jj] = t;
    }
}

// ---------------------------------------------------------------------------
// Pass 3: inverse FFT over k2, scale, transposed float4 store (n2 < 128).
// ---------------------------------------------------------------------------
__global__ void __launch_bounds__(256, 3) k_pass3(float* __restrict__ y) {
    __shared__ float  sre[8][132], sim[8][132];
    __shared__ float2 t256[256];
    const int tid = threadIdx.x, sgn = blockIdx.y, n1b = blockIdx.x * 8;
    t256[tid] = d_t256g[tid];

    const int w = tid >> 5, lane = tid & 31;
    const float2* __restrict__ row =
        (float2*)d_scr4 + (size_t)sgn * N_FFT + (size_t)(n1b + w) * 256;
    float2 v[8];
#pragma unroll
    for (int k = 0; k < 8; ++k) v[k] = row[32 * k + lane];   // coalesced
    __syncthreads();                           // t256 ready

    ifft256_reg(v, t256, lane);                // natural n2 = 32k+lane

#pragma unroll
    for (int k = 0; k < 4; ++k) {              // only n2 < 128 -> n < T
        sre[w][32 * k + lane] = v[k].x * SCALE_INV;
        sim[w][32 * k + lane] = v[k].y * SCALE_INV;
    }
    __syncthreads();

    float4* __restrict__ yr4 = (float4*)(y + (size_t)(2 * sgn)     * T_LEN);
    float4* __restrict__ yi4 = (float4*)(y + (size_t)(2 * sgn + 1) * T_LEN);
    {
        int n1q = tid & 1, n2 = tid >> 1;
        int g4 = (n1b >> 2) + n1q + 64 * n2;
        float4 a, b;
        a.x = sre[4*n1q+0][n2]; a.y = sre[4*n1q+1][n2];
        a.z = sre[4*n1q+2][n2]; a.w = sre[4*n1q+3][n2];
        b.x = sim[4*n1q+0][n2]; b.y = sim[4*n1q+1][n2];
        b.z = sim[4*n1q+2][n2]; b.w = sim[4*n1q+3][n2];
        yr4[g4] = a;
        yi4[g4] = b;
    }
}

// ---------------------------------------------------------------------------
// Filter pass 1: real input, single signal -> d_Htmp[n1*256 + p].
// ---------------------------------------------------------------------------
__global__ void __launch_bounds__(256) k_fpass1(const float* __restrict__ filt) {
    __shared__ float  sre[8][132];
    __shared__ float2 t256[256], tlo[256];
    const int tid = threadIdx.x, n1b = blockIdx.x * 8;
    t256[tid] = d_t256g[tid];
    tlo[tid]  = d_tlog[tid];

#pragma unroll
    for (int it = 0; it < 4; ++it) {
        int idx = tid + it * 256;
        int n1l = idx & 7, n2 = idx >> 3;
        sre[n1l][n2] = filt[n1b + n1l + 256 * n2];   // < 32768 = L
    }
    __syncthreads();

    const int w = tid >> 5, lane = tid & 31;
    float2 v[8];
#pragma unroll
    for (int k = 0; k < 4; ++k) {
        v[k]     = make_float2(sre[w][32 * k + lane], 0.f);
        v[k + 4] = make_float2(0.f, 0.f);
    }
    fft256_reg(v, t256, lane);

    const int n1 = n1b + w;
    float2* __restrict__ out = d_Htmp + (size_t)n1 * 256;
#pragma unroll
    for (int k = 0; k < 8; ++k) {
        int p  = 32 * k + lane;
        int k2 = __brev(p) >> 24;
        int e  = n1 * k2;
        float2 wt = cmul(t256[e >> 8], tlo[e & 255]);
        out[p] = cmul(v[k], wt);
    }
}

// ---------------------------------------------------------------------------
// Filter pass 2: fwd FFT over n1 per p; store positionally d_Hs[p*256 + q].
// ---------------------------------------------------------------------------
__global__ void __launch_bounds__(256) k_fpass2() {
    __shared__ float  sre[8][260], sim[8][260];
    __shared__ float2 t256[256];
    const int tid = threadIdx.x, pb = blockIdx.x * 8;
    t256[tid] = d_t256g[tid];

#pragma unroll
    for (int it = 0; it < 8; ++it) {
        int idx = tid + it * 256;
        int j = idx & 7, n1 = idx >> 3;
        float2 t = d_Htmp[(size_t)n1 * 256 + pb + j];
        sre[j][n1] = t.x;  sim[j][n1] = t.y;
    }
    __syncthreads();

    const int w = tid >> 5, lane = tid & 31;
    float2 v[8];
#pragma unroll
    for (int k = 0; k < 8; ++k)
        v[k] = make_float2(sre[w][32 * k + lane], sim[w][32 * k + lane]);
    fft256_reg(v, t256, lane);

    float2* __restrict__ out = d_Hs + (size_t)(pb + w) * 256;
#pragma unroll
    for (int k = 0; k < 8; ++k) out[32 * k + lane] = v[k];
}

// ---------------------------------------------------------------------------
extern "C" void kernel_launch(void* const* d_in, const int* in_sizes, int n_in,
                              void* d_out, int out_size) {
    (void)out_size;
    const float* x    = (const float*)d_in[0];   // (256, 32768) fp32
    const float* filt = (const float*)d_in[1];   // (1, 32768)   fp32
    if (in_sizes && n_in >= 2 && in_sizes[0] == T_LEN) {  // safety: swapped
        x    = (const float*)d_in[1];
        filt = (const float*)d_in[0];
    }
    float* y = (float*)d_out;                    // (256, 32768) fp32

    k_init  <<<1, 256>>>();
    k_fpass1<<<32, 256>>>(filt);
    k_fpass2<<<32, 256>>>();
    k_pass1 <<<dim3(32, NSIG), 256>>>(x);
    k_pass2 <<<dim3(32, NSIG), 256>>>();
    k_pass3 <<<dim3(32, NSIG), 256>>>(y);
}

// round 11
// speedup vs baseline: 1.1574x; 1.1574x over previous
#include <cuda_runtime.h>
#include <math.h>

// EpochedFutureFill: B=256, T=32768, L=32768 -> n_fft = 65536 = 256*256.
// Four-step FFT convolution, register-resident 256-pt warp FFTs.
// R11: long twiddles W_N^{n1*k2} precomputed in TWO global tables (both
// access orders coalesced, L2-resident) -- removes all scattered smem
// twiddle gathers that dominated pass1/pass2 L1 traffic.
#define T_LEN   32768
#define N_FFT   65536
#define NSIG    128
#define SCALE_INV (1.0f / 65536.0f)

__device__ float4 d_scr4[NSIG * N_FFT / 2];  // 64 MB workspace (16B aligned)
__device__ float2 d_Htmp[N_FFT];             // filter intermediate
__device__ float2 d_Hs[N_FFT];               // filter spectrum [p][q]
__device__ float2 d_t256g[256];              // W_256^j
__device__ float2 d_WL [N_FFT];              // W_N^{n1*brev(p)}, [n1][p]
__device__ float2 d_WLT[N_FFT];              // same values, [p][n1]

__device__ __forceinline__ float2 cmul(float2 a, float2 b) {
    return make_float2(a.x * b.x - a.y * b.y, a.x * b.y + a.y * b.x);
}
__device__ __forceinline__ float2 cmulc(float2 a, float2 b) {  // a * conj(b)
    return make_float2(a.x * b.x + a.y * b.y, a.y * b.x - a.x * b.y);
}
__device__ __forceinline__ void bfly_f(float2& lo, float2& hi, float2 w) {
    float2 a = lo, b = hi;
    lo = make_float2(a.x + b.x, a.y + b.y);
    hi = cmul(make_float2(a.x - b.x, a.y - b.y), w);
}
__device__ __forceinline__ void bfly_i(float2& lo, float2& hi, float2 w) {
    float2 t = cmulc(hi, w);
    float2 a = lo;
    lo = make_float2(a.x + t.x, a.y + t.y);
    hi = make_float2(a.x - t.x, a.y - t.y);
}

// One-time twiddle build: t256 + both long-twiddle tables (65536 entries).
__global__ void k_init() {
    int idx = blockIdx.x * 256 + threadIdx.x;    // grid 256 x 256 = 65536
    int n1 = idx >> 8, p = idx & 255;
    int k2 = __brev(p) >> 24;
    float sn, cs;
    sincospif(-(float)(n1 * k2) / 32768.0f, &sn, &cs);
    float2 wv = make_float2(cs, sn);
    d_WL [idx]          = wv;                    // [n1][p]  (coalesced)
    d_WLT[p * 256 + n1] = wv;                    // [p][n1]  (scattered, 1-time)
    if (idx < 256) {
        sincospif(-(float)idx / 128.0f, &sn, &cs);
        d_t256g[idx] = make_float2(cs, sn);
    }
}

// 256-pt forward DIF FFT, warp-register-resident. v[k] = point 32k+lane.
__device__ __forceinline__ void fft256_reg(float2 v[8],
                                           const float2* __restrict__ t256,
                                           int lane) {
#pragma unroll
    for (int k = 0; k < 4; ++k) bfly_f(v[k], v[k + 4], t256[32 * k + lane]);
    {
        float2 w0 = t256[2 * lane], w1 = t256[64 + 2 * lane];
        bfly_f(v[0], v[2], w0); bfly_f(v[1], v[3], w1);
        bfly_f(v[4], v[6], w0); bfly_f(v[5], v[7], w1);
    }
    {
        float2 w = t256[4 * lane];
        bfly_f(v[0], v[1], w); bfly_f(v[2], v[3], w);
        bfly_f(v[4], v[5], w); bfly_f(v[6], v[7], w);
    }
#pragma unroll
    for (int s = 0; s < 5; ++s) {
        const int d = 16 >> s;
        float2 w = t256[(lane & (d - 1)) * (128 / d)];
        const bool up = (lane & d) != 0;
#pragma unroll
        for (int k = 0; k < 8; ++k) {
            float tr = __shfl_xor_sync(0xffffffffu, v[k].x, d);
            float ti = __shfl_xor_sync(0xffffffffu, v[k].y, d);
            if (up) v[k] = cmul(make_float2(tr - v[k].x, ti - v[k].y), w);
            else    { v[k].x += tr; v[k].y += ti; }
        }
    }
}

// 256-pt inverse (unnormalized, x256), exact reverse graph.
__device__ __forceinline__ void ifft256_reg(float2 v[8],
                                            const float2* __restrict__ t256,
                                            int lane) {
#pragma unroll
    for (int s = 0; s < 5; ++s) {
        const int d = 1 << s;
        float2 w = t256[(lane & (d - 1)) * (128 / d)];
        const bool up = (lane & d) != 0;
#pragma unroll
        for (int k = 0; k < 8; ++k) {
            float2 x = v[k];
            if (up) x = cmulc(x, w);
            float tr = __shfl_xor_sync(0xffffffffu, x.x, d);
            float ti = __shfl_xor_sync(0xffffffffu, x.y, d);
            v[k] = up ? make_float2(tr - x.x, ti - x.y)
                      : make_float2(x.x + tr, x.y + ti);
        }
    }
    {
        float2 w = t256[4 * lane];
        bfly_i(v[0], v[1], w); bfly_i(v[2], v[3], w);
        bfly_i(v[4], v[5], w); bfly_i(v[6], v[7], w);
    }
    {
        float2 w0 = t256[2 * lane], w1 = t256[64 + 2 * lane];
        bfly_i(v[0], v[2], w0); bfly_i(v[1], v[3], w1);
        bfly_i(v[4], v[6], w0); bfly_i(v[5], v[7], w1);
    }
#pragma unroll
    for (int k = 0; k < 4; ++k) bfly_i(v[k], v[k + 4], t256[32 * k + lane]);
}

// ---------------------------------------------------------------------------
// Pass 1: FFT over n2, long twiddle (coalesced d_WL row), store d_scr.
// ---------------------------------------------------------------------------
__global__ void __launch_bounds__(256, 3) k_pass1(const float* __restrict__ x) {
    __shared__ float  sre[8][132], sim[8][132];
    __shared__ float2 t256[256];
    const int tid = threadIdx.x, sgn = blockIdx.y, n1b = blockIdx.x * 8;
    t256[tid] = d_t256g[tid];

    const float4* __restrict__ xr4 =
        (const float4*)(x + (size_t)(2 * sgn)     * T_LEN);
    const float4* __restrict__ xi4 =
        (const float4*)(x + (size_t)(2 * sgn + 1) * T_LEN);
    {
        int n1q = tid & 1, n2 = tid >> 1;
        int g4 = (n1b >> 2) + n1q + 64 * n2;   // float4 index
        float4 a = xr4[g4];
        sre[4*n1q+0][n2] = a.x; sre[4*n1q+1][n2] = a.y;
        sre[4*n1q+2][n2] = a.z; sre[4*n1q+3][n2] = a.w;
        float4 b = xi4[g4];
        sim[4*n1q+0][n2] = b.x; sim[4*n1q+1][n2] = b.y;
        sim[4*n1q+2][n2] = b.z; sim[4*n1q+3][n2] = b.w;
    }
    __syncthreads();

    const int w = tid >> 5, lane = tid & 31;
    float2 v[8];
#pragma unroll
    for (int k = 0; k < 4; ++k) {
        v[k]     = make_float2(sre[w][32 * k + lane], sim[w][32 * k + lane]);
        v[k + 4] = make_float2(0.f, 0.f);      // zero pad [T, N)
    }
    fft256_reg(v, t256, lane);

    const int n1 = n1b + w;
    const float2* __restrict__ WL = d_WL + (size_t)n1 * 256;
    float2* __restrict__ out =
        (float2*)d_scr4 + (size_t)sgn * N_FFT + (size_t)n1 * 256;
#pragma unroll
    for (int k = 0; k < 8; ++k) {
        int p = 32 * k + lane;
        out[p] = cmul(v[k], WL[p]);            // W_N^{n1*k2}, coalesced
    }
}

// ---------------------------------------------------------------------------
// Pass 2 (fused): fwd FFT over n1, multiply Hs, inverse FFT, un-twiddle
// via coalesced d_WLT row. float4 global transposes.
// ---------------------------------------------------------------------------
__global__ void __launch_bounds__(256, 3) k_pass2() {
    __shared__ float  sre[8][260], sim[8][260];   // 260 % 32 == 4
    __shared__ float2 t256[256];
    const int tid = threadIdx.x, sgn = blockIdx.y, pb = blockIdx.x * 8;
    t256[tid] = d_t256g[tid];

    float2* __restrict__ base = (float2*)d_scr4 + (size_t)sgn * N_FFT;
#pragma unroll
    for (int it = 0; it < 4; ++it) {
        int idx = tid + it * 256;
        int jj = idx & 3, n1 = idx >> 2;
        float4 t = *(const float4*)&base[(size_t)n1 * 256 + pb + 2 * jj];
        sre[2*jj  ][n1] = t.x;  sim[2*jj  ][n1] = t.y;
        sre[2*jj+1][n1] = t.z;  sim[2*jj+1][n1] = t.w;
    }
    __syncthreads();

    const int w = tid >> 5, lane = tid & 31;
    float2 v[8];
#pragma unroll
    for (int k = 0; k < 8; ++k)
        v[k] = make_float2(sre[w][32 * k + lane], sim[w][32 * k + lane]);
    __syncthreads();                           // reads done before overwrite

    fft256_reg(v, t256, lane);                 // over n1 -> positions q

    const int p = pb + w;
    const float2* __restrict__ H = d_Hs + (size_t)p * 256;
#pragma unroll
    for (int k = 0; k < 8; ++k) v[k] = cmul(v[k], H[32 * k + lane]);

    ifft256_reg(v, t256, lane);                // -> natural n1

    const float2* __restrict__ WT = d_WLT + (size_t)p * 256;
#pragma unroll
    for (int k = 0; k < 8; ++k) {
        int n1 = 32 * k + lane;
        v[k] = cmulc(v[k], WT[n1]);            // * W_N^{-n1*k2}, coalesced
    }

#pragma unroll
    for (int k = 0; k < 8; ++k) {
        sre[w][32 * k + lane] = v[k].x;
        sim[w][32 * k + lane] = v[k].y;
    }
    __syncthreads();
#pragma unroll
    for (int it = 0; it < 4; ++it) {
        int idx = tid + it * 256;
        int jj = idx & 3, n1 = idx >> 2;
        float4 t;
        t.x = sre[2*jj  ][n1];  t.y = sim[2*jj  ][n1];
        t.z = sre[2*jj+1][n1];  t.w = sim[2*jj+1][n1];
        *(float4*)&base[(size_t)n1 * 256 + pb + 2 * jj] = t;
    }
}

// ---------------------------------------------------------------------------
// Pass 3: inverse FFT over k2, scale, transposed float4 store (n2 < 128).
// ---------------------------------------------------------------------------
__global__ void __launch_bounds__(256, 3) k_pass3(float* __restrict__ y) {
    __shared__ float  sre[8][132], sim[8][132];
    __shared__ float2 t256[256];
    const int tid = threadIdx.x, sgn = blockIdx.y, n1b = blockIdx.x * 8;
    t256[tid] = d_t256g[tid];

    const int w = tid >> 5, lane = tid & 31;
    const float2* __restrict__ row =
        (float2*)d_scr4 + (size_t)sgn * N_FFT + (size_t)(n1b + w) * 256;
    float2 v[8];
#pragma unroll
    for (int k = 0; k < 8; ++k) v[k] = row[32 * k + lane];   // coalesced
    __syncthreads();                           // t256 ready

    ifft256_reg(v, t256, lane);                // natural n2 = 32k+lane

#pragma unroll
    for (int k = 0; k < 4; ++k) {              // only n2 < 128 -> n < T
        sre[w][32 * k + lane] = v[k].x * SCALE_INV;
        sim[w][32 * k + lane] = v[k].y * SCALE_INV;
    }
    __syncthreads();

    float4* __restrict__ yr4 = (float4*)(y + (size_t)(2 * sgn)     * T_LEN);
    float4* __restrict__ yi4 = (float4*)(y + (size_t)(2 * sgn + 1) * T_LEN);
    {
        int n1q = tid & 1, n2 = tid >> 1;
        int g4 = (n1b >> 2) + n1q + 64 * n2;
        float4 a, b;
        a.x = sre[4*n1q+0][n2]; a.y = sre[4*n1q+1][n2];
        a.z = sre[4*n1q+2][n2]; a.w = sre[4*n1q+3][n2];
        b.x = sim[4*n1q+0][n2]; b.y = sim[4*n1q+1][n2];
        b.z = sim[4*n1q+2][n2]; b.w = sim[4*n1q+3][n2];
        yr4[g4] = a;
        yi4[g4] = b;
    }
}

// ---------------------------------------------------------------------------
// Filter pass 1: real input, single signal -> d_Htmp[n1*256 + p].
// ---------------------------------------------------------------------------
__global__ void __launch_bounds__(256) k_fpass1(const float* __restrict__ filt) {
    __shared__ float  sre[8][132];
    __shared__ float2 t256[256];
    const int tid = threadIdx.x, n1b = blockIdx.x * 8;
    t256[tid] = d_t256g[tid];

#pragma unroll
    for (int it = 0; it < 4; ++it) {
        int idx = tid + it * 256;
        int n1l = idx & 7, n2 = idx >> 3;
        sre[n1l][n2] = filt[n1b + n1l + 256 * n2];   // < 32768 = L
    }
    __syncthreads();

    const int w = tid >> 5, lane = tid & 31;
    float2 v[8];
#pragma unroll
    for (int k = 0; k < 4; ++k) {
        v[k]     = make_float2(sre[w][32 * k + lane], 0.f);
        v[k + 4] = make_float2(0.f, 0.f);
    }
    fft256_reg(v, t256, lane);

    const int n1 = n1b + w;
    const float2* __restrict__ WL = d_WL + (size_t)n1 * 256;
    float2* __restrict__ out = d_Htmp + (size_t)n1 * 256;
#pragma unroll
    for (int k = 0; k < 8; ++k) {
        int p = 32 * k + lane;
        out[p] = cmul(v[k], WL[p]);
    }
}

// ---------------------------------------------------------------------------
// Filter pass 2: fwd FFT over n1 per p; store positionally d_Hs[p*256 + q].
// ---------------------------------------------------------------------------
__global__ void __launch_bounds__(256) k_fpass2() {
    __shared__ float  sre[8][260], sim[8][260];
    __shared__ float2 t256[256];
    const int tid = threadIdx.x, pb = blockIdx.x * 8;
    t256[tid] = d_t256g[tid];

#pragma unroll
    for (int it = 0; it < 8; ++it) {
        int idx = tid + it * 256;
        int j = idx & 7, n1 = idx >> 3;
        float2 t = d_Htmp[(size_t)n1 * 256 + pb + j];
        sre[j][n1] = t.x;  sim[j][n1] = t.y;
    }
    __syncthreads();

    const int w = tid >> 5, lane = tid & 31;
    float2 v[8];
#pragma unroll
    for (int k = 0; k < 8; ++k)
        v[k] = make_float2(sre[w][32 * k + lane], sim[w][32 * k + lane]);
    fft256_reg(v, t256, lane);

    float2* __restrict__ out = d_Hs + (size_t)(pb + w) * 256;
#pragma unroll
    for (int k = 0; k < 8; ++k) out[32 * k + lane] = v[k];
}

// ---------------------------------------------------------------------------
extern "C" void kernel_launch(void* const* d_in, const int* in_sizes, int n_in,
                              void* d_out, int out_size) {
    (void)out_size;
    const float* x    = (const float*)d_in[0];   // (256, 32768) fp32
    const float* filt = (const float*)d_in[1];   // (1, 32768)   fp32
    if (in_sizes && n_in >= 2 && in_sizes[0] == T_LEN) {  // safety: swapped
        x    = (const float*)d_in[1];
        filt = (const float*)d_in[0];
    }
    float* y = (float*)d_out;                    // (256, 32768) fp32

    k_init  <<<256, 256>>>();
    k_fpass1<<<32, 256>>>(filt);
    k_fpass2<<<32, 256>>>();
    k_pass1 <<<dim3(32, NSIG), 256>>>(x);
    k_pass2 <<<dim3(32, NSIG), 256>>>();
    k_pass3 <<<dim3(32, NSIG), 256>>>(y);
}